// round 9
// baseline (speedup 1.0000x reference)
#include <cuda_runtime.h>
#include <cstdint>

// Problem constants
#define B_TOT  2048
#define S_LEN  256
#define DIN    3
#define HID    128
#define D_OUT  6
#define DT_F   0.1f

// 16 rows/CTA, 128 CTAs, 512 threads, 1 CTA/SM.
// Warp w: nb = w&3 (32-neuron block), kq = w>>2 (K-slice: 32 cols).
// Lane: r = lane&3 (row sub-slot), q = lane>>2 (neuron quad in block).
// Thread: 4 neurons (2 packed pairs) x 4 rows (r,r+4,r+8,r+12) x 32 cols.
// h loads are LANE-SPREAD over 4 rows (4x16B = 64B/warp = 1 wavefront) and
// 8-way broadcast over q -> each LDS.128 feeds 16 FFMA2.
// K reduced 4-way via SMEM partials; finish thread owns fixed (quad, row),
// old-h and x-proj params in registers. 2 barriers/step.
#define ROWS   16
#define NCTA   (B_TOT / ROWS)        // 128
#define NTHR   512
#define SPC    264                   // splat row pitch (256 data + 8 skew floats)
#define PPITCH 132                   // partial row pitch (128 + 4 skew)

#define XSZ    (ROWS * S_LEN * DIN)  // 12288 floats
#define HSPSZ  (ROWS * SPC)          // 4224 floats per buffer
#define PARTSZ (4 * ROWS * PPITCH)   // 8448 floats
#define SMEMF  (XSZ + 2 * HSPSZ + PARTSZ)   // 29184 floats = 116736 B

typedef unsigned long long u64;

// ---- packed f32x2 ops ----
__device__ __forceinline__ u64 fma2(u64 a, u64 b, u64 c) {
    u64 d;
    asm("fma.rn.f32x2 %0, %1, %2, %3;" : "=l"(d) : "l"(a), "l"(b), "l"(c));
    return d;
}
__device__ __forceinline__ u64 add2(u64 a, u64 b) {
    u64 d;
    asm("add.rn.f32x2 %0, %1, %2;" : "=l"(d) : "l"(a), "l"(b));
    return d;
}
__device__ __forceinline__ u64 pk(float lo, float hi) {
    u64 v;
    asm("mov.b64 %0, {%1, %2};" : "=l"(v) : "f"(lo), "f"(hi));
    return v;
}
__device__ __forceinline__ void upk(u64 v, float& lo, float& hi) {
    asm("mov.b64 {%0, %1}, %2;" : "=f"(lo), "=f"(hi) : "l"(v));
}

// Accurate-enough tanh: ex2.approx + fast divide; abs err ~1e-6.
__device__ __forceinline__ float fast_tanh(float x) {
    float ax = fminf(fabsf(x), 15.0f);
    float e  = __expf(2.0f * ax);
    float t  = 1.0f - __fdividef(2.0f, e + 1.0f);
    return copysignf(t, x);
}

// softplus(x) = max(x,0) + log1p(exp(-|x|))  (stable, accurate)
__device__ __forceinline__ float softplus_acc(float x) {
    return fmaxf(x, 0.0f) + log1pf(__expf(-fabsf(x)));
}

extern __shared__ float smem_dyn[];

__global__ void __launch_bounds__(NTHR, 1)
cfc_kernel(const float* __restrict__ x,        // [B, S, 3]
           const float* __restrict__ W_xh,     // [128, 3]
           const float* __restrict__ W_hh,     // [128, 128]
           const float* __restrict__ b_hh,     // [128]
           const float* __restrict__ log_tau,  // [128]
           const float* __restrict__ fc_W,     // [6, 128]
           const float* __restrict__ fc_b,     // [6]
           float* __restrict__ out)            // [B, 6]
{
    float* xsh  = smem_dyn;            // x tile
    float* hsp0 = xsh + XSZ;           // splatted h, buffer 0
    float* hsp1 = hsp0 + HSPSZ;        // splatted h, buffer 1
    float* part = hsp1 + HSPSZ;        // partials [kq][row][neuron]

    const int tid  = threadIdx.x;
    const int lane = tid & 31;
    const int w    = tid >> 5;
    const int r    = lane & 3;            // row sub-slot
    const int q    = lane >> 2;           // neuron quad within block (0..7)
    const int nb   = w & 3;               // neuron block (32 neurons)
    const int kq   = w >> 2;              // K slice (cols kq*32 .. +31)
    const int n0   = nb * 32 + q * 4;     // first of this thread's 4 neurons
    const int cb   = blockIdx.x * ROWS;   // global batch-row base

    // ---- W_hh: 2 packed neuron-pairs x 32 cols -> 64 u64 = 128 regs ----
    u64 W01[32], W23[32];
    #pragma unroll
    for (int c = 0; c < 32; c++) {
        W01[c] = pk(W_hh[(n0 + 0) * HID + kq * 32 + c], W_hh[(n0 + 1) * HID + kq * 32 + c]);
        W23[c] = pk(W_hh[(n0 + 2) * HID + kq * 32 + c], W_hh[(n0 + 3) * HID + kq * 32 + c]);
    }

    // ---- finish assignment: thread owns (quad fn, row frow) ----
    const int fn   = tid >> 4;            // neuron quad 0..31
    const int frow = tid & 15;            // row 0..15
    // finish params in registers
    float fw[12], fb[4], fa[4], ho[4];
    #pragma unroll
    for (int i = 0; i < 4; i++) {
        fw[3 * i + 0] = W_xh[(4 * fn + i) * 3 + 0];
        fw[3 * i + 1] = W_xh[(4 * fn + i) * 3 + 1];
        fw[3 * i + 2] = W_xh[(4 * fn + i) * 3 + 2];
        fb[i] = b_hh[4 * fn + i];
        fa[i] = DT_F / (softplus_acc(log_tau[4 * fn + i]) + 0.001f);
        ho[i] = 0.0f;
    }

    // ---- stage x tile; zero h buffers ----
    {
        const float* src = x + (size_t)cb * (S_LEN * DIN);
        for (int i = tid; i < XSZ; i += NTHR) xsh[i] = src[i];
    }
    for (int i = tid; i < 2 * HSPSZ; i += NTHR) hsp0[i] = 0.0f;
    __syncthreads();

    // ================= sequential scan over S =================
    for (int s = 0; s < S_LEN; s++) {
        const float* hcur = (s & 1) ? hsp1 : hsp0;
        float*       hnxt = (s & 1) ? hsp0 : hsp1;

        // ---- matvec: 4 rows x 4 neurons x 32 cols, 8 independent chains ----
        u64 a01[4], a23[4];
        #pragma unroll
        for (int rs = 0; rs < 4; rs++) { a01[rs] = 0ull; a23[rs] = 0ull; }

        const float* hb = hcur + r * SPC + kq * 64;   // this lane's base row
        #pragma unroll
        for (int c2 = 0; c2 < 16; c2++) {             // 2 splat cols per iter
            #pragma unroll
            for (int rs = 0; rs < 4; rs++) {
                // lane-spread load: 4 rows x 16B across warp = 1 wavefront
                ulonglong2 hv = *reinterpret_cast<const ulonglong2*>(
                    hb + rs * (4 * SPC) + c2 * 4);
                a01[rs] = fma2(W01[2 * c2],     hv.x, a01[rs]);
                a23[rs] = fma2(W23[2 * c2],     hv.x, a23[rs]);
                a01[rs] = fma2(W01[2 * c2 + 1], hv.y, a01[rs]);
                a23[rs] = fma2(W23[2 * c2 + 1], hv.y, a23[rs]);
            }
        }

        // ---- publish partials: one STS.128 per row ----
        #pragma unroll
        for (int rs = 0; rs < 4; rs++) {
            const int row = r + 4 * rs;
            ulonglong2 v; v.x = a01[rs]; v.y = a23[rs];
            *reinterpret_cast<ulonglong2*>(part + (kq * ROWS + row) * PPITCH + n0) = v;
        }
        __syncthreads();

        // ---- finish: reduce 4 K-slices for (fn, frow), tanh, leaky update ----
        {
            u64 s01 = 0ull, s23 = 0ull;
            #pragma unroll
            for (int ks = 0; ks < 4; ks++) {
                ulonglong2 pv = *reinterpret_cast<const ulonglong2*>(
                    part + (ks * ROWS + frow) * PPITCH + 4 * fn);
                s01 = add2(s01, pv.x);
                s23 = add2(s23, pv.y);
            }
            float z[4];
            upk(s01, z[0], z[1]);
            upk(s23, z[2], z[3]);

            const float* xr = xsh + frow * (S_LEN * DIN) + s * 3;
            float x0 = xr[0], x1 = xr[1], x2 = xr[2];

            u64 sp[4];
            #pragma unroll
            for (int i = 0; i < 4; i++) {
                float zi = z[i] + fmaf(fw[3 * i], x0,
                              fmaf(fw[3 * i + 1], x1,
                              fmaf(fw[3 * i + 2], x2, fb[i])));
                float f = fast_tanh(zi);
                ho[i] = fmaf(fa[i], f - ho[i], ho[i]);
                sp[i] = pk(ho[i], ho[i]);
            }
            // splat-store 4 neurons (8 floats) for row frow
            float* hd = hnxt + frow * SPC + 8 * fn;
            ulonglong2 o;
            o.x = sp[0]; o.y = sp[1];
            *reinterpret_cast<ulonglong2*>(hd)     = o;
            o.x = sp[2]; o.y = sp[3];
            *reinterpret_cast<ulonglong2*>(hd + 4) = o;
        }
        __syncthreads();
    }

    // ================= output head: softplus(h_T @ fc_W^T + fc_b) =================
    const float* hf = hsp0;   // S_LEN even -> final state in buffer 0 (splatted)
    if (tid < ROWS * D_OUT) {
        const int rr = tid / D_OUT;
        const int o  = tid % D_OUT;
        float z = fc_b[o];
        const float* wrow = fc_W + o * HID;
        const float* hrow = hf + rr * SPC;
        #pragma unroll
        for (int j = 0; j < HID; j++)
            z = fmaf(wrow[j], hrow[2 * j], z);
        out[(cb + rr) * D_OUT + o] = softplus_acc(z);
    }
}

extern "C" void kernel_launch(void* const* d_in, const int* in_sizes, int n_in,
                              void* d_out, int out_size) {
    const float* x       = (const float*)d_in[0];
    const float* W_xh    = (const float*)d_in[1];
    const float* W_hh    = (const float*)d_in[2];
    const float* b_hh    = (const float*)d_in[3];
    const float* log_tau = (const float*)d_in[4];
    const float* fc_W    = (const float*)d_in[5];
    const float* fc_b    = (const float*)d_in[6];
    float* out = (float*)d_out;

    const size_t shmem = (size_t)SMEMF * sizeof(float);  // 116736 B
    cudaFuncSetAttribute(cfc_kernel, cudaFuncAttributeMaxDynamicSharedMemorySize, (int)shmem);

    cfc_kernel<<<NCTA, NTHR, shmem>>>(x, W_xh, W_hh, b_hh, log_tau, fc_W, fc_b, out);
}

// round 11
// speedup vs baseline: 2.0314x; 2.0314x over previous
#include <cuda_runtime.h>
#include <cstdint>

// Problem constants
#define B_TOT  2048
#define S_LEN  256
#define DIN    3
#define HID    128
#define D_OUT  6
#define DT_F   0.1f

// 14 rows/CTA, 147 CTAs, 256 threads, 1 CTA/SM (256-reg budget -> no spills).
// Matvec thread: np = tid&15 (neuron OCT n0=8np), ks = (tid>>4)&7 (16 cols),
// rh = tid>>7 (7-row half). Each broadcast LDS.128 feeds 8 FFMA2.
// Finish: 896 (pair,row) tasks over ALL 256 threads; thread owns ONE neuron
// pair p = tid&63 for rows (tid>>6)+{0,4,8,12} -> x-proj/bias/leak/old-h all
// live in registers, no global loads inside the scan.
#define ROWS   14
#define RPG    7
#define NCTA   ((B_TOT + ROWS - 1) / ROWS)   // 147
#define NTHR   256
#define SPC    (2 * HID)                     // splat pitch: 256 floats

#define XSZ    (ROWS * S_LEN * DIN)          // 10752 floats
#define HSPSZ  (ROWS * SPC)                  // 3584 floats per buffer
#define PARTSZ (8 * ROWS * HID)              // 14336 floats
#define SMEMF  (XSZ + 2 * HSPSZ + PARTSZ)    // 32256 floats = 129024 B

typedef unsigned long long u64;

// ---- packed f32x2 ops ----
__device__ __forceinline__ u64 fma2(u64 a, u64 b, u64 c) {
    u64 d;
    asm("fma.rn.f32x2 %0, %1, %2, %3;" : "=l"(d) : "l"(a), "l"(b), "l"(c));
    return d;
}
__device__ __forceinline__ u64 add2(u64 a, u64 b) {
    u64 d;
    asm("add.rn.f32x2 %0, %1, %2;" : "=l"(d) : "l"(a), "l"(b));
    return d;
}
__device__ __forceinline__ u64 pk(float lo, float hi) {
    u64 v;
    asm("mov.b64 %0, {%1, %2};" : "=l"(v) : "f"(lo), "f"(hi));
    return v;
}
__device__ __forceinline__ void upk(u64 v, float& lo, float& hi) {
    asm("mov.b64 {%0, %1}, %2;" : "=f"(lo), "=f"(hi) : "l"(v));
}

// Accurate-enough tanh: ex2.approx + fast divide; abs err ~1e-6.
__device__ __forceinline__ float fast_tanh(float x) {
    float ax = fminf(fabsf(x), 15.0f);
    float e  = __expf(2.0f * ax);
    float t  = 1.0f - __fdividef(2.0f, e + 1.0f);
    return copysignf(t, x);
}

// softplus(x) = max(x,0) + log1p(exp(-|x|))  (stable, accurate)
__device__ __forceinline__ float softplus_acc(float x) {
    return fmaxf(x, 0.0f) + log1pf(__expf(-fabsf(x)));
}

extern __shared__ float smem_dyn[];

__global__ void __launch_bounds__(NTHR, 1)
cfc_kernel(const float* __restrict__ x,        // [B, S, 3]
           const float* __restrict__ W_xh,     // [128, 3]
           const float* __restrict__ W_hh,     // [128, 128]
           const float* __restrict__ b_hh,     // [128]
           const float* __restrict__ log_tau,  // [128]
           const float* __restrict__ fc_W,     // [6, 128]
           const float* __restrict__ fc_b,     // [6]
           float* __restrict__ out)            // [B, 6]
{
    float* xsh  = smem_dyn;            // x tile
    float* hsp0 = xsh + XSZ;           // splatted h, buffer 0
    float* hsp1 = hsp0 + HSPSZ;        // splatted h, buffer 1
    float* part = hsp1 + HSPSZ;        // partials [ks][row][neuron]

    const int tid  = threadIdx.x;
    const int np   = tid & 15;            // neuron oct: n0 = 8np .. 8np+7
    const int ks   = (tid >> 4) & 7;      // K slice: cols [16ks, 16ks+16)
    const int rh   = tid >> 7;            // row half
    const int n0   = 8 * np;
    const int rowb = rh * RPG;
    const int cb   = blockIdx.x * ROWS;   // global batch-row base

    // ---- W_hh: 4 neuron-pairs x 16 cols -> 64 u64 = 128 regs ----
    u64 W0[16], W1[16], W2[16], W3[16];
    #pragma unroll
    for (int c = 0; c < 16; c++) {
        const int col = 16 * ks + c;
        W0[c] = pk(W_hh[(n0 + 0) * HID + col], W_hh[(n0 + 1) * HID + col]);
        W1[c] = pk(W_hh[(n0 + 2) * HID + col], W_hh[(n0 + 3) * HID + col]);
        W2[c] = pk(W_hh[(n0 + 4) * HID + col], W_hh[(n0 + 5) * HID + col]);
        W3[c] = pk(W_hh[(n0 + 6) * HID + col], W_hh[(n0 + 7) * HID + col]);
    }

    // ---- finish: thread owns pair p = tid&63 for rows r0+{0,4,8,12} ----
    const int p  = tid & 63;              // neuron pair (2p, 2p+1)
    const int r0 = tid >> 6;              // base row (0..3)
    const int nA = 2 * p, nB = 2 * p + 1;
    const float wxa0 = W_xh[nA * 3 + 0], wxa1 = W_xh[nA * 3 + 1], wxa2 = W_xh[nA * 3 + 2];
    const float wxb0 = W_xh[nB * 3 + 0], wxb1 = W_xh[nB * 3 + 1], wxb2 = W_xh[nB * 3 + 2];
    const float bba = b_hh[nA], bbb = b_hh[nB];
    const float aaA = DT_F / (softplus_acc(log_tau[nA]) + 0.001f);
    const float aaB = DT_F / (softplus_acc(log_tau[nB]) + 0.001f);
    float hoA[4], hoB[4];                 // old h per task, registers
    #pragma unroll
    for (int t = 0; t < 4; t++) { hoA[t] = 0.0f; hoB[t] = 0.0f; }
    const int ntask = (tid < 128) ? 4 : 3;   // rows 12,13 covered by tid<128

    // ---- stage x tile (zero-pad partial last CTA); zero h buffers ----
    {
        const float* src = x + (size_t)cb * (S_LEN * DIN);
        int lim = (B_TOT - cb) * (S_LEN * DIN);
        if (lim > XSZ) lim = XSZ;
        for (int i = tid; i < XSZ; i += NTHR)
            xsh[i] = (i < lim) ? src[i] : 0.0f;
    }
    for (int i = tid; i < 2 * HSPSZ; i += NTHR) hsp0[i] = 0.0f;
    __syncthreads();

    // ================= sequential scan over S =================
    for (int s = 0; s < S_LEN; s++) {
        const float* hcur = (s & 1) ? hsp1 : hsp0;
        float*       hnxt = (s & 1) ? hsp0 : hsp1;

        const float* hb = hcur + rowb * SPC + 32 * ks;
        float* pb = part + (ks * ROWS + rowb) * HID + n0;

        // ---- matvec batch A: rows 0..3 of this half ----
        {
            u64 a0[4], a1[4], a2[4], a3[4];
            #pragma unroll
            for (int r = 0; r < 4; r++) { a0[r] = 0; a1[r] = 0; a2[r] = 0; a3[r] = 0; }
            #pragma unroll
            for (int c2 = 0; c2 < 8; c2++) {
                #pragma unroll
                for (int r = 0; r < 4; r++) {
                    ulonglong2 hv = *reinterpret_cast<const ulonglong2*>(hb + r * SPC + c2 * 4);
                    a0[r] = fma2(W0[2 * c2],     hv.x, a0[r]);
                    a1[r] = fma2(W1[2 * c2],     hv.x, a1[r]);
                    a2[r] = fma2(W2[2 * c2],     hv.x, a2[r]);
                    a3[r] = fma2(W3[2 * c2],     hv.x, a3[r]);
                    a0[r] = fma2(W0[2 * c2 + 1], hv.y, a0[r]);
                    a1[r] = fma2(W1[2 * c2 + 1], hv.y, a1[r]);
                    a2[r] = fma2(W2[2 * c2 + 1], hv.y, a2[r]);
                    a3[r] = fma2(W3[2 * c2 + 1], hv.y, a3[r]);
                }
            }
            #pragma unroll
            for (int r = 0; r < 4; r++) {
                ulonglong2 v1; v1.x = a0[r]; v1.y = a1[r];
                ulonglong2 v2; v2.x = a2[r]; v2.y = a3[r];
                *reinterpret_cast<ulonglong2*>(pb + r * HID)     = v1;
                *reinterpret_cast<ulonglong2*>(pb + r * HID + 4) = v2;
            }
        }
        // ---- matvec batch B: rows 4..6 of this half ----
        {
            u64 a0[3], a1[3], a2[3], a3[3];
            #pragma unroll
            for (int r = 0; r < 3; r++) { a0[r] = 0; a1[r] = 0; a2[r] = 0; a3[r] = 0; }
            #pragma unroll
            for (int c2 = 0; c2 < 8; c2++) {
                #pragma unroll
                for (int r = 0; r < 3; r++) {
                    ulonglong2 hv = *reinterpret_cast<const ulonglong2*>(hb + (4 + r) * SPC + c2 * 4);
                    a0[r] = fma2(W0[2 * c2],     hv.x, a0[r]);
                    a1[r] = fma2(W1[2 * c2],     hv.x, a1[r]);
                    a2[r] = fma2(W2[2 * c2],     hv.x, a2[r]);
                    a3[r] = fma2(W3[2 * c2],     hv.x, a3[r]);
                    a0[r] = fma2(W0[2 * c2 + 1], hv.y, a0[r]);
                    a1[r] = fma2(W1[2 * c2 + 1], hv.y, a1[r]);
                    a2[r] = fma2(W2[2 * c2 + 1], hv.y, a2[r]);
                    a3[r] = fma2(W3[2 * c2 + 1], hv.y, a3[r]);
                }
            }
            #pragma unroll
            for (int r = 0; r < 3; r++) {
                ulonglong2 v1; v1.x = a0[r]; v1.y = a1[r];
                ulonglong2 v2; v2.x = a2[r]; v2.y = a3[r];
                *reinterpret_cast<ulonglong2*>(pb + (4 + r) * HID)     = v1;
                *reinterpret_cast<ulonglong2*>(pb + (4 + r) * HID + 4) = v2;
            }
        }
        __syncthreads();

        // ---- finish: ntask rows for this thread's pair p ----
        #pragma unroll
        for (int t = 0; t < 4; t++) {
            if (t >= ntask) break;
            const int row = r0 + 4 * t;
            // reduce 8 K-slices (u64 per slice at float offset 2p)
            u64 zz = 0ull;
            #pragma unroll
            for (int q = 0; q < 8; q++)
                zz = add2(zz, *reinterpret_cast<const u64*>(
                    part + (q * ROWS + row) * HID + 2 * p));
            float zA, zB;
            upk(zz, zA, zB);
            const float* xr = xsh + row * (S_LEN * DIN) + s * 3;
            float x0 = xr[0], x1 = xr[1], x2 = xr[2];
            zA += fmaf(wxa0, x0, fmaf(wxa1, x1, fmaf(wxa2, x2, bba)));
            zB += fmaf(wxb0, x0, fmaf(wxb1, x1, fmaf(wxb2, x2, bbb)));
            float fA = fast_tanh(zA);
            float fB = fast_tanh(zB);
            hoA[t] = fmaf(aaA, fA - hoA[t], hoA[t]);
            hoB[t] = fmaf(aaB, fB - hoB[t], hoB[t]);
            // splat store: neurons 2p,2p+1 -> 16B at float offset 4p
            ulonglong2 o;
            o.x = pk(hoA[t], hoA[t]);
            o.y = pk(hoB[t], hoB[t]);
            *reinterpret_cast<ulonglong2*>(hnxt + row * SPC + 4 * p) = o;
        }
        __syncthreads();
    }

    // ================= output head: softplus(h_T @ fc_W^T + fc_b) =================
    const float* hf = hsp0;   // S_LEN even -> final state in buffer 0 (splatted)
    if (tid < ROWS * D_OUT) {
        const int rr = tid / D_OUT;
        const int o  = tid % D_OUT;
        const int grow = cb + rr;
        if (grow < B_TOT) {
            float z = fc_b[o];
            const float* wrow = fc_W + o * HID;
            const float* hrow = hf + rr * SPC;
            #pragma unroll
            for (int j = 0; j < HID; j++)
                z = fmaf(wrow[j], hrow[2 * j], z);
            out[grow * D_OUT + o] = softplus_acc(z);
        }
    }
}

extern "C" void kernel_launch(void* const* d_in, const int* in_sizes, int n_in,
                              void* d_out, int out_size) {
    const float* x       = (const float*)d_in[0];
    const float* W_xh    = (const float*)d_in[1];
    const float* W_hh    = (const float*)d_in[2];
    const float* b_hh    = (const float*)d_in[3];
    const float* log_tau = (const float*)d_in[4];
    const float* fc_W    = (const float*)d_in[5];
    const float* fc_b    = (const float*)d_in[6];
    float* out = (float*)d_out;

    const size_t shmem = (size_t)SMEMF * sizeof(float);  // 129024 B
    cudaFuncSetAttribute(cfc_kernel, cudaFuncAttributeMaxDynamicSharedMemorySize, (int)shmem);

    cfc_kernel<<<NCTA, NTHR, shmem>>>(x, W_xh, W_hh, b_hh, log_tau, fc_W, fc_b, out);
}

// round 12
// speedup vs baseline: 2.2396x; 1.1024x over previous
#include <cuda_runtime.h>
#include <cstdint>

// Problem constants
#define B_TOT  2048
#define S_LEN  256
#define DIN    3
#define HID    128
#define D_OUT  6
#define DT_F   0.1f

// 14 rows/CTA, 147 CTAs, 256 threads, 1 CTA/SM.
// TWO INDEPENDENT 128-thread GROUPS: group rh owns rows rh*7..rh*7+6 end to end
// (matvec, partials, finish) and syncs only itself via bar.sync rh+1, 128.
// Groups drift: one group's finish overlaps the other's matvec on each SMSP.
// Matvec thread: np = tid&15 (neuron OCT n0=8np), ks = (tid>>4)&7 (16 cols).
// Each broadcast LDS.128 (splatted h) feeds 8 FFMA2.
// Finish (in-group): gtid=tid&127, pair p=gtid&63, rsel=gtid>>6 ->
// rows rowb+rsel+2t; x-proj/bias/leak/old-h all in registers.
#define ROWS   14
#define RPG    7
#define NCTA   ((B_TOT + ROWS - 1) / ROWS)   // 147
#define NTHR   256
#define SPC    (2 * HID)                     // splat pitch: 256 floats

#define XSZ    (ROWS * S_LEN * DIN)          // 10752 floats
#define HSPSZ  (ROWS * SPC)                  // 3584 floats per buffer
#define PARTSZ (8 * ROWS * HID)              // 14336 floats
#define SMEMF  (XSZ + 2 * HSPSZ + PARTSZ)    // 32256 floats = 129024 B

typedef unsigned long long u64;

// ---- packed f32x2 ops ----
__device__ __forceinline__ u64 fma2(u64 a, u64 b, u64 c) {
    u64 d;
    asm("fma.rn.f32x2 %0, %1, %2, %3;" : "=l"(d) : "l"(a), "l"(b), "l"(c));
    return d;
}
__device__ __forceinline__ u64 add2(u64 a, u64 b) {
    u64 d;
    asm("add.rn.f32x2 %0, %1, %2;" : "=l"(d) : "l"(a), "l"(b));
    return d;
}
__device__ __forceinline__ u64 pk(float lo, float hi) {
    u64 v;
    asm("mov.b64 %0, {%1, %2};" : "=l"(v) : "f"(lo), "f"(hi));
    return v;
}
__device__ __forceinline__ void upk(u64 v, float& lo, float& hi) {
    asm("mov.b64 {%0, %1}, %2;" : "=f"(lo), "=f"(hi) : "l"(v));
}

// Accurate-enough tanh: ex2.approx + fast divide; abs err ~1e-6.
__device__ __forceinline__ float fast_tanh(float x) {
    float ax = fminf(fabsf(x), 15.0f);
    float e  = __expf(2.0f * ax);
    float t  = 1.0f - __fdividef(2.0f, e + 1.0f);
    return copysignf(t, x);
}

// softplus(x) = max(x,0) + log1p(exp(-|x|))  (stable, accurate)
__device__ __forceinline__ float softplus_acc(float x) {
    return fmaxf(x, 0.0f) + log1pf(__expf(-fabsf(x)));
}

extern __shared__ float smem_dyn[];

__global__ void __launch_bounds__(NTHR, 1)
cfc_kernel(const float* __restrict__ x,        // [B, S, 3]
           const float* __restrict__ W_xh,     // [128, 3]
           const float* __restrict__ W_hh,     // [128, 128]
           const float* __restrict__ b_hh,     // [128]
           const float* __restrict__ log_tau,  // [128]
           const float* __restrict__ fc_W,     // [6, 128]
           const float* __restrict__ fc_b,     // [6]
           float* __restrict__ out)            // [B, 6]
{
    float* xsh  = smem_dyn;            // x tile
    float* hsp0 = xsh + XSZ;           // splatted h, buffer 0
    float* hsp1 = hsp0 + HSPSZ;        // splatted h, buffer 1
    float* part = hsp1 + HSPSZ;        // partials [ks][row][neuron]

    const int tid  = threadIdx.x;
    const int np   = tid & 15;            // neuron oct: n0 = 8np .. 8np+7
    const int ks   = (tid >> 4) & 7;      // K slice: cols [16ks, 16ks+16)
    const int rh   = tid >> 7;            // GROUP id (row half)
    const int n0   = 8 * np;
    const int rowb = rh * RPG;            // group's base row
    const int cb   = blockIdx.x * ROWS;   // global batch-row base

    // ---- W_hh: 4 neuron-pairs x 16 cols -> 64 u64 = 128 regs ----
    u64 W0[16], W1[16], W2[16], W3[16];
    #pragma unroll
    for (int c = 0; c < 16; c++) {
        const int col = 16 * ks + c;
        W0[c] = pk(W_hh[(n0 + 0) * HID + col], W_hh[(n0 + 1) * HID + col]);
        W1[c] = pk(W_hh[(n0 + 2) * HID + col], W_hh[(n0 + 3) * HID + col]);
        W2[c] = pk(W_hh[(n0 + 4) * HID + col], W_hh[(n0 + 5) * HID + col]);
        W3[c] = pk(W_hh[(n0 + 6) * HID + col], W_hh[(n0 + 7) * HID + col]);
    }

    // ---- finish assignment (IN-GROUP): pair p, row subset within group ----
    const int gtid = tid & 127;
    const int p    = gtid & 63;           // neuron pair (2p, 2p+1)
    const int rsel = gtid >> 6;           // 0: rows {0,2,4,6}; 1: rows {1,3,5}
    const int ntask = rsel ? 3 : 4;
    const int nA = 2 * p, nB = 2 * p + 1;
    const float wxa0 = W_xh[nA * 3 + 0], wxa1 = W_xh[nA * 3 + 1], wxa2 = W_xh[nA * 3 + 2];
    const float wxb0 = W_xh[nB * 3 + 0], wxb1 = W_xh[nB * 3 + 1], wxb2 = W_xh[nB * 3 + 2];
    const float bba = b_hh[nA], bbb = b_hh[nB];
    const float aaA = DT_F / (softplus_acc(log_tau[nA]) + 0.001f);
    const float aaB = DT_F / (softplus_acc(log_tau[nB]) + 0.001f);
    float hoA[4], hoB[4];                 // old h per task, registers
    #pragma unroll
    for (int t = 0; t < 4; t++) { hoA[t] = 0.0f; hoB[t] = 0.0f; }

    // ---- stage x tile (zero-pad partial last CTA); zero h buffers ----
    {
        const float* src = x + (size_t)cb * (S_LEN * DIN);
        int lim = (B_TOT - cb) * (S_LEN * DIN);
        if (lim > XSZ) lim = XSZ;
        for (int i = tid; i < XSZ; i += NTHR)
            xsh[i] = (i < lim) ? src[i] : 0.0f;
    }
    for (int i = tid; i < 2 * HSPSZ; i += NTHR) hsp0[i] = 0.0f;
    __syncthreads();

    // ================= sequential scan over S (group-independent) =================
    for (int s = 0; s < S_LEN; s++) {
        const float* hcur = (s & 1) ? hsp1 : hsp0;
        float*       hnxt = (s & 1) ? hsp0 : hsp1;

        const float* hb = hcur + rowb * SPC + 32 * ks;
        float* pb = part + (ks * ROWS + rowb) * HID + n0;

        // ---- matvec batch A: rows 0..3 of this group ----
        {
            u64 a0[4], a1[4], a2[4], a3[4];
            #pragma unroll
            for (int r = 0; r < 4; r++) { a0[r] = 0; a1[r] = 0; a2[r] = 0; a3[r] = 0; }
            #pragma unroll
            for (int c2 = 0; c2 < 8; c2++) {
                #pragma unroll
                for (int r = 0; r < 4; r++) {
                    ulonglong2 hv = *reinterpret_cast<const ulonglong2*>(hb + r * SPC + c2 * 4);
                    a0[r] = fma2(W0[2 * c2],     hv.x, a0[r]);
                    a1[r] = fma2(W1[2 * c2],     hv.x, a1[r]);
                    a2[r] = fma2(W2[2 * c2],     hv.x, a2[r]);
                    a3[r] = fma2(W3[2 * c2],     hv.x, a3[r]);
                    a0[r] = fma2(W0[2 * c2 + 1], hv.y, a0[r]);
                    a1[r] = fma2(W1[2 * c2 + 1], hv.y, a1[r]);
                    a2[r] = fma2(W2[2 * c2 + 1], hv.y, a2[r]);
                    a3[r] = fma2(W3[2 * c2 + 1], hv.y, a3[r]);
                }
            }
            #pragma unroll
            for (int r = 0; r < 4; r++) {
                ulonglong2 v1; v1.x = a0[r]; v1.y = a1[r];
                ulonglong2 v2; v2.x = a2[r]; v2.y = a3[r];
                *reinterpret_cast<ulonglong2*>(pb + r * HID)     = v1;
                *reinterpret_cast<ulonglong2*>(pb + r * HID + 4) = v2;
            }
        }
        // ---- matvec batch B: rows 4..6 of this group ----
        {
            u64 a0[3], a1[3], a2[3], a3[3];
            #pragma unroll
            for (int r = 0; r < 3; r++) { a0[r] = 0; a1[r] = 0; a2[r] = 0; a3[r] = 0; }
            #pragma unroll
            for (int c2 = 0; c2 < 8; c2++) {
                #pragma unroll
                for (int r = 0; r < 3; r++) {
                    ulonglong2 hv = *reinterpret_cast<const ulonglong2*>(hb + (4 + r) * SPC + c2 * 4);
                    a0[r] = fma2(W0[2 * c2],     hv.x, a0[r]);
                    a1[r] = fma2(W1[2 * c2],     hv.x, a1[r]);
                    a2[r] = fma2(W2[2 * c2],     hv.x, a2[r]);
                    a3[r] = fma2(W3[2 * c2],     hv.x, a3[r]);
                    a0[r] = fma2(W0[2 * c2 + 1], hv.y, a0[r]);
                    a1[r] = fma2(W1[2 * c2 + 1], hv.y, a1[r]);
                    a2[r] = fma2(W2[2 * c2 + 1], hv.y, a2[r]);
                    a3[r] = fma2(W3[2 * c2 + 1], hv.y, a3[r]);
                }
            }
            #pragma unroll
            for (int r = 0; r < 3; r++) {
                ulonglong2 v1; v1.x = a0[r]; v1.y = a1[r];
                ulonglong2 v2; v2.x = a2[r]; v2.y = a3[r];
                *reinterpret_cast<ulonglong2*>(pb + (4 + r) * HID)     = v1;
                *reinterpret_cast<ulonglong2*>(pb + (4 + r) * HID + 4) = v2;
            }
        }
        // group-scoped barrier: partials of THIS group's rows ready
        asm volatile("bar.sync %0, 128;" :: "r"(rh + 1) : "memory");

        // ---- finish: ntask rows of this group for pair p ----
        #pragma unroll
        for (int t = 0; t < 4; t++) {
            if (t >= ntask) break;
            const int row = rowb + rsel + 2 * t;
            u64 zz = 0ull;
            #pragma unroll
            for (int q = 0; q < 8; q++)
                zz = add2(zz, *reinterpret_cast<const u64*>(
                    part + (q * ROWS + row) * HID + 2 * p));
            float zA, zB;
            upk(zz, zA, zB);
            const float* xr = xsh + row * (S_LEN * DIN) + s * 3;
            float x0 = xr[0], x1 = xr[1], x2 = xr[2];
            zA += fmaf(wxa0, x0, fmaf(wxa1, x1, fmaf(wxa2, x2, bba)));
            zB += fmaf(wxb0, x0, fmaf(wxb1, x1, fmaf(wxb2, x2, bbb)));
            float fA = fast_tanh(zA);
            float fB = fast_tanh(zB);
            hoA[t] = fmaf(aaA, fA - hoA[t], hoA[t]);
            hoB[t] = fmaf(aaB, fB - hoB[t], hoB[t]);
            ulonglong2 o;
            o.x = pk(hoA[t], hoA[t]);
            o.y = pk(hoB[t], hoB[t]);
            *reinterpret_cast<ulonglong2*>(hnxt + row * SPC + 4 * p) = o;
        }
        // group-scoped barrier: this group's h(s+1) rows complete
        asm volatile("bar.sync %0, 128;" :: "r"(rh + 1) : "memory");
    }

    __syncthreads();   // join groups before the head

    // ================= output head: softplus(h_T @ fc_W^T + fc_b) =================
    const float* hf = hsp0;   // S_LEN even -> final state in buffer 0 (splatted)
    if (tid < ROWS * D_OUT) {
        const int rr = tid / D_OUT;
        const int o  = tid % D_OUT;
        const int grow = cb + rr;
        if (grow < B_TOT) {
            float z = fc_b[o];
            const float* wrow = fc_W + o * HID;
            const float* hrow = hf + rr * SPC;
            #pragma unroll
            for (int j = 0; j < HID; j++)
                z = fmaf(wrow[j], hrow[2 * j], z);
            out[grow * D_OUT + o] = softplus_acc(z);
        }
    }
}

extern "C" void kernel_launch(void* const* d_in, const int* in_sizes, int n_in,
                              void* d_out, int out_size) {
    const float* x       = (const float*)d_in[0];
    const float* W_xh    = (const float*)d_in[1];
    const float* W_hh    = (const float*)d_in[2];
    const float* b_hh    = (const float*)d_in[3];
    const float* log_tau = (const float*)d_in[4];
    const float* fc_W    = (const float*)d_in[5];
    const float* fc_b    = (const float*)d_in[6];
    float* out = (float*)d_out;

    const size_t shmem = (size_t)SMEMF * sizeof(float);  // 129024 B
    cudaFuncSetAttribute(cfc_kernel, cudaFuncAttributeMaxDynamicSharedMemorySize, (int)shmem);

    cfc_kernel<<<NCTA, NTHR, shmem>>>(x, W_xh, W_hh, b_hh, log_tau, fc_W, fc_b, out);
}